// round 1
// baseline (speedup 1.0000x reference)
#include <cuda_runtime.h>
#include <cuda_bf16.h>
#include <math_constants.h>

#define BB 2
#define NSEQ 2048
#define DIN 256
#define NH 8
#define DH 32
#define DMODEL 256
#define MROWS (BB*NSEQ)

__device__ float g_Q[BB*NH*NSEQ*DH];
__device__ float g_K[BB*NH*NSEQ*DH];
__device__ float g_V[BB*NH*NSEQ*DH];
__device__ float g_O[MROWS*DMODEL];

// C[m][n] = sum_k A[m][k] * B[n][k]
// WHICH: 0->g_Q, 1->g_K, 2->g_V (heads layout); 3 -> Cout row-major + bias, A taken from g_O
template<int WHICH>
__global__ void gemm_nt_kernel(const float* __restrict__ Ain,
                               const float* __restrict__ B,
                               const float* __restrict__ bias,
                               float* __restrict__ Cout,
                               int M, int N, int K)
{
    const float* A = (WHICH == 3) ? (const float*)g_O : Ain;

    constexpr int BM = 64, BN = 64, BK = 16;
    __shared__ float As[BK][BM + 1];
    __shared__ float Bs[BK][BN + 1];

    const int t  = threadIdx.x;
    const int tx = t & 15;
    const int ty = t >> 4;
    const int bm = blockIdx.y * BM;
    const int bn = blockIdx.x * BN;

    float acc[4][4];
#pragma unroll
    for (int i = 0; i < 4; i++)
#pragma unroll
        for (int j = 0; j < 4; j++) acc[i][j] = 0.f;

    for (int k0 = 0; k0 < K; k0 += BK) {
#pragma unroll
        for (int i = 0; i < 4; i++) {
            int idx = t + i * 256;
            int r = idx >> 4;
            int c = idx & 15;
            As[c][r] = A[(size_t)(bm + r) * K + k0 + c];
            Bs[c][r] = B[(size_t)(bn + r) * K + k0 + c];
        }
        __syncthreads();
#pragma unroll
        for (int kk = 0; kk < BK; kk++) {
            float a[4], b[4];
#pragma unroll
            for (int i = 0; i < 4; i++) { a[i] = As[kk][ty * 4 + i]; b[i] = Bs[kk][tx * 4 + i]; }
#pragma unroll
            for (int i = 0; i < 4; i++)
#pragma unroll
                for (int j = 0; j < 4; j++) acc[i][j] += a[i] * b[j];
        }
        __syncthreads();
    }

#pragma unroll
    for (int i = 0; i < 4; i++) {
        int m = bm + ty * 4 + i;
#pragma unroll
        for (int j = 0; j < 4; j++) {
            int n = bn + tx * 4 + j;
            float v = acc[i][j];
            if (WHICH == 3) {
                v += bias[n];
                Cout[(size_t)m * N + n] = v;
            } else {
                int b   = m >> 11;
                int row = m & (NSEQ - 1);
                int h   = n >> 5;
                int d   = n & 31;
                float* dst = (WHICH == 0) ? g_Q : (WHICH == 1) ? g_K : g_V;
                dst[(((size_t)(b * NH + h)) * NSEQ + row) * DH + d] = v;
            }
        }
    }
}

// Fused masked attention with online softmax.
// grid: (N/32, H, B). block: 256 threads = 8 warps.
__global__ void attn_kernel(const float* __restrict__ adj)
{
    constexpr int QT = 32, KT = 64;
    const int q0 = blockIdx.x * QT;
    const int h  = blockIdx.y;
    const int b  = blockIdx.z;

    const float* Qh = g_Q + ((size_t)(b * NH + h)) * NSEQ * DH;
    const float* Kh = g_K + ((size_t)(b * NH + h)) * NSEQ * DH;
    const float* Vh = g_V + ((size_t)(b * NH + h)) * NSEQ * DH;
    const float* adjb = adj + ((size_t)(b * NSEQ + q0)) * NSEQ;

    __shared__ float Qs[QT][DH + 1];
    __shared__ float Ks[KT][DH + 1];
    __shared__ float Vs[KT][DH];
    __shared__ float Ss[QT][KT + 1];
    __shared__ float Adjs[QT][KT];

    const int t    = threadIdx.x;
    const int w    = t >> 5;
    const int lane = t & 31;

#pragma unroll
    for (int i = 0; i < 4; i++) {
        int idx = t + i * 256;
        int r = idx >> 5, c = idx & 31;
        Qs[r][c] = Qh[(size_t)(q0 + r) * DH + c];
    }

    float m_r[4], l_r[4], acc[4];
#pragma unroll
    for (int r = 0; r < 4; r++) { m_r[r] = -CUDART_INF_F; l_r[r] = 0.f; acc[r] = 0.f; }

    const float scale = 0.17677669529663687f;

    for (int k0 = 0; k0 < NSEQ; k0 += KT) {
        __syncthreads();
#pragma unroll
        for (int i = 0; i < 8; i++) {
            int idx = t + i * 256;
            int r = idx >> 5, c = idx & 31;
            Ks[r][c] = Kh[(size_t)(k0 + r) * DH + c];
            Vs[r][c] = Vh[(size_t)(k0 + r) * DH + c];
            int ar = idx >> 6, ac = idx & 63;
            Adjs[ar][ac] = adjb[(size_t)ar * NSEQ + k0 + ac];
        }
        __syncthreads();

        {
            const int qi = t >> 3;
            const int kb = t & 7;
            float sv[8];
#pragma unroll
            for (int u = 0; u < 8; u++) {
                int kj = kb + u * 8;
                float s = 0.f;
#pragma unroll
                for (int d = 0; d < DH; d++) s += Qs[qi][d] * Ks[kj][d];
                sv[u] = (Adjs[qi][kj] != 0.f) ? s * scale : -CUDART_INF_F;
            }
#pragma unroll
            for (int u = 0; u < 8; u++) Ss[qi][kb + u * 8] = sv[u];
        }
        __syncthreads();

#pragma unroll
        for (int r = 0; r < 4; r++) {
            const int row = w * 4 + r;
            float s0 = Ss[row][lane];
            float s1 = Ss[row][lane + 32];
            float tmax = fmaxf(s0, s1);
#pragma unroll
            for (int off = 16; off > 0; off >>= 1)
                tmax = fmaxf(tmax, __shfl_xor_sync(0xffffffffu, tmax, off));
            float nm = fmaxf(m_r[r], tmax);
            if (nm != -CUDART_INF_F) {
                float corr = __expf(m_r[r] - nm);
                float e0 = __expf(s0 - nm);
                float e1 = __expf(s1 - nm);
                float ps = e0 + e1;
#pragma unroll
                for (int off = 16; off > 0; off >>= 1)
                    ps += __shfl_xor_sync(0xffffffffu, ps, off);
                l_r[r] = l_r[r] * corr + ps;
                m_r[r] = nm;
                Ss[row][lane]      = e0;
                Ss[row][lane + 32] = e1;
                __syncwarp();
                float a = acc[r] * corr;
#pragma unroll
                for (int j = 0; j < KT; j++) a += Ss[row][j] * Vs[j][lane];
                acc[r] = a;
            }
        }
    }

#pragma unroll
    for (int r = 0; r < 4; r++) {
        int q = q0 + w * 4 + r;
        g_O[((size_t)(b * NSEQ + q)) * DMODEL + h * DH + lane] = acc[r] / l_r[r];
    }
}

extern "C" void kernel_launch(void* const* d_in, const int* in_sizes, int n_in,
                              void* d_out, int out_size)
{
    const float* x   = (const float*)d_in[0];
    const float* adj = (const float*)d_in[1];
    const float* Wq  = (const float*)d_in[2];
    const float* Wk  = (const float*)d_in[3];
    const float* Wv  = (const float*)d_in[4];
    const float* Wo  = (const float*)d_in[5];
    const float* bo  = (const float*)d_in[6];
    float* out = (float*)d_out;

    dim3 gemm_grid(DMODEL / 64, MROWS / 64);
    gemm_nt_kernel<0><<<gemm_grid, 256>>>(x, Wq, nullptr, nullptr, MROWS, DMODEL, DIN);
    gemm_nt_kernel<1><<<gemm_grid, 256>>>(x, Wk, nullptr, nullptr, MROWS, DMODEL, DIN);
    gemm_nt_kernel<2><<<gemm_grid, 256>>>(x, Wv, nullptr, nullptr, MROWS, DMODEL, DIN);

    attn_kernel<<<dim3(NSEQ / 32, NH, BB), 256>>>(adj);

    gemm_nt_kernel<3><<<gemm_grid, 256>>>(nullptr, Wo, bo, out, MROWS, DMODEL, DMODEL);
}

// round 5
// speedup vs baseline: 3.0066x; 3.0066x over previous
#include <cuda_runtime.h>
#include <cuda_bf16.h>
#include <math_constants.h>

#define BB 2
#define NSEQ 2048
#define DIN 256
#define NH 8
#define DH 32
#define DMODEL 256
#define MROWS (BB*NSEQ)

__device__ float g_Q[BB*NH*NSEQ*DH];
__device__ float g_K[BB*NH*NSEQ*DH];
__device__ float g_V[BB*NH*NSEQ*DH];
__device__ float g_O[MROWS*DMODEL];

// ---------------------------------------------------------------------------
// fp32 SIMT GEMM for projections: C[m][n] = sum_k A[m][k]*B[n][k]
// WHICH: 0->g_Q, 1->g_K, 2->g_V ([b][h][n][dh] layout); 3 -> out + bias (A = g_O)
// ---------------------------------------------------------------------------
template<int WHICH>
__global__ void gemm_nt_kernel(const float* __restrict__ Ain,
                               const float* __restrict__ B,
                               const float* __restrict__ bias,
                               float* __restrict__ Cout,
                               int M, int N, int K)
{
    const float* A = (WHICH == 3) ? (const float*)g_O : Ain;

    constexpr int BM = 64, BN = 64, BK = 16;
    __shared__ float As[BK][BM + 1];
    __shared__ float Bs[BK][BN + 1];

    const int t  = threadIdx.x;
    const int tx = t & 15;
    const int ty = t >> 4;
    const int bm = blockIdx.y * BM;
    const int bn = blockIdx.x * BN;

    float acc[4][4];
#pragma unroll
    for (int i = 0; i < 4; i++)
#pragma unroll
        for (int j = 0; j < 4; j++) acc[i][j] = 0.f;

    for (int k0 = 0; k0 < K; k0 += BK) {
#pragma unroll
        for (int i = 0; i < 4; i++) {
            int idx = t + i * 256;
            int r = idx >> 4;
            int c = idx & 15;
            As[c][r] = A[(size_t)(bm + r) * K + k0 + c];
            Bs[c][r] = B[(size_t)(bn + r) * K + k0 + c];
        }
        __syncthreads();
#pragma unroll
        for (int kk = 0; kk < BK; kk++) {
            float a[4], b[4];
#pragma unroll
            for (int i = 0; i < 4; i++) { a[i] = As[kk][ty * 4 + i]; b[i] = Bs[kk][tx * 4 + i]; }
#pragma unroll
            for (int i = 0; i < 4; i++)
#pragma unroll
                for (int j = 0; j < 4; j++) acc[i][j] += a[i] * b[j];
        }
        __syncthreads();
    }

#pragma unroll
    for (int i = 0; i < 4; i++) {
        int m = bm + ty * 4 + i;
#pragma unroll
        for (int j = 0; j < 4; j++) {
            int n = bn + tx * 4 + j;
            float v = acc[i][j];
            if (WHICH == 3) {
                v += bias[n];
                Cout[(size_t)m * N + n] = v;
            } else {
                int b   = m >> 11;
                int row = m & (NSEQ - 1);
                int h   = n >> 5;
                int d   = n & 31;
                float* dst = (WHICH == 0) ? g_Q : (WHICH == 1) ? g_K : g_V;
                dst[(((size_t)(b * NH + h)) * NSEQ + row) * DH + d] = v;
            }
        }
    }
}

// ---------------------------------------------------------------------------
// tf32 tensor-core flash attention.
// grid (NSEQ/64, NH, BB), block 128 (4 warps). Warp w owns q rows [64*bx + 16w, +16).
// ---------------------------------------------------------------------------
__device__ __forceinline__ unsigned f2tf32(float x) {
    unsigned r;
    asm("cvt.rna.tf32.f32 %0, %1;" : "=r"(r) : "f"(x));
    return r;
}

__device__ __forceinline__ void mma_tf32(float& c0, float& c1, float& c2, float& c3,
                                         unsigned a0, unsigned a1, unsigned a2, unsigned a3,
                                         unsigned b0, unsigned b1)
{
    asm volatile("mma.sync.aligned.m16n8k8.row.col.f32.tf32.tf32.f32 "
                 "{%0,%1,%2,%3}, {%4,%5,%6,%7}, {%8,%9}, {%0,%1,%2,%3};"
                 : "+f"(c0), "+f"(c1), "+f"(c2), "+f"(c3)
                 : "r"(a0), "r"(a1), "r"(a2), "r"(a3), "r"(b0), "r"(b1));
}

// smem strides (in 32-bit words) chosen for conflict-free fragment loads:
//  Qs/Ks stride 36: bank = 4*g + c (distinct over g in 0..7, c in 0..3)
//  Vs stride 40:    bank = 8*c + g (distinct)
//  AdjPs stride 66
#define QS_STRIDE 36
#define KS_STRIDE 36
#define VS_STRIDE 40
#define AP_STRIDE 66

__global__ void __launch_bounds__(128, 4) attn_tc_kernel(const float* __restrict__ adj)
{
    __shared__ unsigned Qs[64 * QS_STRIDE];
    __shared__ unsigned Ks[64 * KS_STRIDE];
    __shared__ unsigned Vs[64 * VS_STRIDE];
    __shared__ unsigned AdjPs[64 * AP_STRIDE];   // adj tile, later reused as per-warp P tile

    const int q0 = blockIdx.x * 64;
    const int h  = blockIdx.y;
    const int b  = blockIdx.z;

    const float* Qh = g_Q + ((size_t)(b * NH + h)) * NSEQ * DH;
    const float* Kh = g_K + ((size_t)(b * NH + h)) * NSEQ * DH;
    const float* Vh = g_V + ((size_t)(b * NH + h)) * NSEQ * DH;
    const unsigned* adjb = (const unsigned*)(adj + ((size_t)(b * NSEQ + q0)) * NSEQ);

    const int t    = threadIdx.x;
    const int w    = t >> 5;
    const int lane = t & 31;
    const int g    = lane >> 2;   // group id (row within fragment)
    const int c4   = lane & 3;    // thread-in-group (col within fragment)

    // Stage Q (pre-rounded tf32), coalesced
#pragma unroll
    for (int i = 0; i < 16; i++) {
        int idx = t + i * 128;
        int r = idx >> 5, c = idx & 31;
        Qs[r * QS_STRIDE + c] = f2tf32(Qh[(size_t)(q0 + r) * DH + c]);
    }
    __syncthreads();

    // Resident Q fragments: qa[kt][0..3], kt = k-tile over DH (4 x 8)
    unsigned qa[4][4];
#pragma unroll
    for (int kt = 0; kt < 4; kt++) {
        int base = (w * 16 + g) * QS_STRIDE + kt * 8 + c4;
        qa[kt][0] = Qs[base];
        qa[kt][1] = Qs[base + 8 * QS_STRIDE];
        qa[kt][2] = Qs[base + 4];
        qa[kt][3] = Qs[base + 8 * QS_STRIDE + 4];
    }

    float m0 = -1e30f, m1 = -1e30f, l0 = 0.f, l1 = 0.f;
    float o[4][4];
#pragma unroll
    for (int nt = 0; nt < 4; nt++)
#pragma unroll
        for (int j = 0; j < 4; j++) o[nt][j] = 0.f;

    const float scale = 0.17677669529663687f;   // 1/sqrt(32)

    for (int k0 = 0; k0 < NSEQ; k0 += 64) {
        __syncthreads();
        // Stage K, V (tf32) and adj (raw bits), coalesced
#pragma unroll
        for (int i = 0; i < 16; i++) {
            int idx = t + i * 128;
            int r = idx >> 5, c = idx & 31;
            Ks[r * KS_STRIDE + c] = f2tf32(Kh[(size_t)(k0 + r) * DH + c]);
            Vs[r * VS_STRIDE + c] = f2tf32(Vh[(size_t)(k0 + r) * DH + c]);
        }
#pragma unroll
        for (int i = 0; i < 32; i++) {
            int idx = t + i * 128;
            int r = idx >> 6, c = idx & 63;
            AdjPs[r * AP_STRIDE + c] = adjb[(size_t)r * NSEQ + k0 + c];
        }
        __syncthreads();

        // ---- S = Q K^T (16 x 64 per warp) ----
        float s[8][4];
#pragma unroll
        for (int nt = 0; nt < 8; nt++) {
            float c0 = 0.f, c1 = 0.f, c2 = 0.f, c3 = 0.f;
#pragma unroll
            for (int kt = 0; kt < 4; kt++) {
                int kb = (nt * 8 + g) * KS_STRIDE + kt * 8 + c4;
                unsigned b0 = Ks[kb];
                unsigned b1 = Ks[kb + 4];
                mma_tf32(c0, c1, c2, c3, qa[kt][0], qa[kt][1], qa[kt][2], qa[kt][3], b0, b1);
            }
            s[nt][0] = c0; s[nt][1] = c1; s[nt][2] = c2; s[nt][3] = c3;
        }

        // ---- mask + scale ----
        const unsigned* ar0 = AdjPs + (w * 16 + g) * AP_STRIDE + 2 * c4;
        const unsigned* ar1 = ar0 + 8 * AP_STRIDE;
#pragma unroll
        for (int nt = 0; nt < 8; nt++) {
            s[nt][0] = ar0[nt * 8]     ? s[nt][0] * scale : -1e30f;
            s[nt][1] = ar0[nt * 8 + 1] ? s[nt][1] * scale : -1e30f;
            s[nt][2] = ar1[nt * 8]     ? s[nt][2] * scale : -1e30f;
            s[nt][3] = ar1[nt * 8 + 1] ? s[nt][3] * scale : -1e30f;
        }

        // ---- online softmax (rows g and g+8) ----
        float tm0 = -1e30f, tm1 = -1e30f;
#pragma unroll
        for (int nt = 0; nt < 8; nt++) {
            tm0 = fmaxf(tm0, fmaxf(s[nt][0], s[nt][1]));
            tm1 = fmaxf(tm1, fmaxf(s[nt][2], s[nt][3]));
        }
        tm0 = fmaxf(tm0, __shfl_xor_sync(0xffffffffu, tm0, 1));
        tm0 = fmaxf(tm0, __shfl_xor_sync(0xffffffffu, tm0, 2));
        tm1 = fmaxf(tm1, __shfl_xor_sync(0xffffffffu, tm1, 1));
        tm1 = fmaxf(tm1, __shfl_xor_sync(0xffffffffu, tm1, 2));

        float nm0 = fmaxf(m0, tm0);
        float nm1 = fmaxf(m1, tm1);
        float corr0 = __expf(m0 - nm0);
        float corr1 = __expf(m1 - nm1);

        float ps0 = 0.f, ps1 = 0.f;
#pragma unroll
        for (int nt = 0; nt < 8; nt++) {
            s[nt][0] = __expf(s[nt][0] - nm0);
            s[nt][1] = __expf(s[nt][1] - nm0);
            s[nt][2] = __expf(s[nt][2] - nm1);
            s[nt][3] = __expf(s[nt][3] - nm1);
            ps0 += s[nt][0] + s[nt][1];
            ps1 += s[nt][2] + s[nt][3];
        }
        ps0 += __shfl_xor_sync(0xffffffffu, ps0, 1);
        ps0 += __shfl_xor_sync(0xffffffffu, ps0, 2);
        ps1 += __shfl_xor_sync(0xffffffffu, ps1, 1);
        ps1 += __shfl_xor_sync(0xffffffffu, ps1, 2);

        l0 = l0 * corr0 + ps0;
        l1 = l1 * corr1 + ps1;
        m0 = nm0;
        m1 = nm1;

#pragma unroll
        for (int nt = 0; nt < 4; nt++) {
            o[nt][0] *= corr0; o[nt][1] *= corr0;
            o[nt][2] *= corr1; o[nt][3] *= corr1;
        }

        // ---- write P into (warp-private) AdjPs region as tf32 ----
        __syncwarp();
        unsigned* pr0 = AdjPs + (w * 16 + g) * AP_STRIDE + 2 * c4;
        unsigned* pr1 = pr0 + 8 * AP_STRIDE;
#pragma unroll
        for (int nt = 0; nt < 8; nt++) {
            pr0[nt * 8]     = f2tf32(s[nt][0]);
            pr0[nt * 8 + 1] = f2tf32(s[nt][1]);
            pr1[nt * 8]     = f2tf32(s[nt][2]);
            pr1[nt * 8 + 1] = f2tf32(s[nt][3]);
        }
        __syncwarp();

        // ---- O += P V  (16 x 32 per warp) ----
#pragma unroll
        for (int kt = 0; kt < 8; kt++) {
            int pb = (w * 16 + g) * AP_STRIDE + kt * 8 + c4;
            unsigned a0 = AdjPs[pb];
            unsigned a1 = AdjPs[pb + 8 * AP_STRIDE];
            unsigned a2 = AdjPs[pb + 4];
            unsigned a3 = AdjPs[pb + 8 * AP_STRIDE + 4];
#pragma unroll
            for (int nt = 0; nt < 4; nt++) {
                unsigned b0 = Vs[(kt * 8 + c4) * VS_STRIDE + nt * 8 + g];
                unsigned b1 = Vs[(kt * 8 + c4 + 4) * VS_STRIDE + nt * 8 + g];
                mma_tf32(o[nt][0], o[nt][1], o[nt][2], o[nt][3], a0, a1, a2, a3, b0, b1);
            }
        }
    }

    // ---- epilogue: normalize, write concat layout ----
    float inv0 = 1.f / l0;
    float inv1 = 1.f / l1;
    int qr0 = q0 + w * 16 + g;
    int qr1 = qr0 + 8;
    float* or0 = g_O + ((size_t)(b * NSEQ + qr0)) * DMODEL + h * DH + 2 * c4;
    float* or1 = g_O + ((size_t)(b * NSEQ + qr1)) * DMODEL + h * DH + 2 * c4;
#pragma unroll
    for (int nt = 0; nt < 4; nt++) {
        float2 v0 = make_float2(o[nt][0] * inv0, o[nt][1] * inv0);
        float2 v1 = make_float2(o[nt][2] * inv1, o[nt][3] * inv1);
        *(float2*)(or0 + nt * 8) = v0;
        *(float2*)(or1 + nt * 8) = v1;
    }
}

// ---------------------------------------------------------------------------

extern "C" void kernel_launch(void* const* d_in, const int* in_sizes, int n_in,
                              void* d_out, int out_size)
{
    const float* x   = (const float*)d_in[0];
    const float* adj = (const float*)d_in[1];
    const float* Wq  = (const float*)d_in[2];
    const float* Wk  = (const float*)d_in[3];
    const float* Wv  = (const float*)d_in[4];
    const float* Wo  = (const float*)d_in[5];
    const float* bo  = (const float*)d_in[6];
    float* out = (float*)d_out;

    dim3 gemm_grid(DMODEL / 64, MROWS / 64);
    gemm_nt_kernel<0><<<gemm_grid, 256>>>(x, Wq, nullptr, nullptr, MROWS, DMODEL, DIN);
    gemm_nt_kernel<1><<<gemm_grid, 256>>>(x, Wk, nullptr, nullptr, MROWS, DMODEL, DIN);
    gemm_nt_kernel<2><<<gemm_grid, 256>>>(x, Wv, nullptr, nullptr, MROWS, DMODEL, DIN);

    attn_tc_kernel<<<dim3(NSEQ / 64, NH, BB), 128>>>(adj);

    gemm_nt_kernel<3><<<gemm_grid, 256>>>(nullptr, Wo, bo, out, MROWS, DMODEL, DMODEL);
}